// round 11
// baseline (speedup 1.0000x reference)
#include <cuda_runtime.h>
#include <cstdint>
#include <math.h>

// Shapes (fixed by the problem)
#define NSENT 4096
#define L     512
#define LQ    32
#define D     30
#define AF    10
#define KK    4

#define TPB 480   // 480*4 % 30 == 0 -> fixed channel phase per thread

// Precomputed tables / question-side results
__device__ float g_W1sum[D * D];
__device__ float g_W2sum[D * D];
__device__ float g_A1[D * D * 6];
__device__ float g_qraw[D];
__device__ float g_q1g[D];
__device__ float g_q2g[D];
__device__ float g_inv_nraw, g_inv_n1, g_inv_n2;
__device__ float g_costs[NSENT];
__device__ int   g_ctr;

// ---------------------------------------------------------------------------
// Kernel 1 (prep): tables into SMEM + gmem; question side from SMEM.
// ---------------------------------------------------------------------------
__global__ void prep_kernel(const float* __restrict__ qe,
                            const float* __restrict__ w1, const float* __restrict__ b1,
                            const float* __restrict__ w2, const float* __restrict__ b2)
{
    __shared__ float sW1[D * D], sW2[D * D], sA[D * D * 6];
    __shared__ float Sq[32], xbq[6][32], Tq[32];

    int tid = threadIdx.x; // 960
    if (tid == 0) g_ctr = 0;

    if (tid < D * D) {
        const float* w = w1 + tid * KK;
        float w0 = w[0], wv1 = w[1], wv2 = w[2], w3 = w[3];
        float ws = w0 + wv1 + wv2 + w3;
        sW1[tid] = ws; g_W1sum[tid] = ws;
        const float* v = w2 + tid * KK;
        float vs = v[0] + v[1] + v[2] + v[3];
        sW2[tid] = vs; g_W2sum[tid] = vs;
        float a0 = 3.f * w3 + 2.f * wv2 + wv1;
        float a1 = 2.f * w3 + wv2;
        float a2 = w3;
        float a3 = w0;
        float a4 = 2.f * w0 + wv1;
        float a5 = 3.f * w0 + 2.f * wv1 + wv2;
        float* As = sA + tid * 6;  float* Ag = g_A1 + tid * 6;
        As[0] = a0; Ag[0] = a0;  As[1] = a1; Ag[1] = a1;
        As[2] = a2; Ag[2] = a2;  As[3] = a3; Ag[3] = a3;
        As[4] = a4; Ag[4] = a4;  As[5] = a5; Ag[5] = a5;
    }

    if (tid < D) {
        float s = 0.f;
        for (int t = 0; t < LQ; t++) s += qe[t * D + tid];
        Sq[tid] = s;
        xbq[0][tid] = qe[0 * D + tid];
        xbq[1][tid] = qe[1 * D + tid];
        xbq[2][tid] = qe[2 * D + tid];
        xbq[3][tid] = qe[(LQ - 3) * D + tid];
        xbq[4][tid] = qe[(LQ - 2) * D + tid];
        xbq[5][tid] = qe[(LQ - 1) * D + tid];
    }
    __syncthreads();

    if (tid < 32) {
        const int o = tid;
        const float invLq3 = 1.f / (float)(LQ + 3);
        float q1 = 0.f, Tv = 0.f;
        if (o < D) {
            float ds = 0.f, bc = 0.f;
            for (int j = 0; j < D; j++) ds += sW1[o * D + j] * Sq[j];
            for (int j = 0; j < D; j++) {
                const float* A = sA + (o * D + j) * 6;
                #pragma unroll
                for (int m = 0; m < 6; m++) bc += A[m] * xbq[m][j];
            }
            q1 = b1[o] + ds * invLq3;
            Tv = (float)LQ * b1[o] + ds - 0.25f * bc;
        }
        Tq[o] = Tv;
        __syncwarp();

        float q2 = 0.f;
        if (o < D) {
            float d2 = 0.f;
            for (int j = 0; j < D; j++) d2 += sW2[o * D + j] * Tq[j];
            q2 = b2[o] + d2 * invLq3;
            g_qraw[o] = Sq[o];
            g_q1g[o] = q1;
            g_q2g[o] = q2;
        }
        __syncwarp();

        float n0 = (o < D) ? Sq[o] * Sq[o] : 0.f;
        float n1 = q1 * q1;
        float n2 = q2 * q2;
        #pragma unroll
        for (int off = 16; off; off >>= 1) {
            n0 += __shfl_down_sync(0xffffffffu, n0, off);
            n1 += __shfl_down_sync(0xffffffffu, n1, off);
            n2 += __shfl_down_sync(0xffffffffu, n2, off);
        }
        if (o == 0) {
            g_inv_nraw = rsqrtf(n0);
            g_inv_n1 = rsqrtf(n1);
            g_inv_n2 = rsqrtf(n2);
        }
    }
}

// ---------------------------------------------------------------------------
// Fused kernel: batched 8-deep LDG stream + atomic-free reduce + tail math.
// ---------------------------------------------------------------------------
__global__ __launch_bounds__(TPB, 2) void fused_kernel(
    const float* __restrict__ se, const float* __restrict__ gaf,
    const int* __restrict__ labels,
    const float* __restrict__ b1, const float* __restrict__ b2,
    const float* __restrict__ lw, const float* __restrict__ lb,
    float* __restrict__ out)
{
    __shared__ float4 part4[TPB];
    __shared__ float S[32], xb[6 * 32], T[32];
    __shared__ int last;

    const int n = blockIdx.x;
    const int tid = threadIdx.x;

    // Batched stream: all 8 loads issued before any accumulation (MLP=8)
    const float4* p = reinterpret_cast<const float4*>(se) + (size_t)n * (L * D / 4);
    float4 v0 = __ldcs(p + tid + TPB * 0);
    float4 v1 = __ldcs(p + tid + TPB * 1);
    float4 v2 = __ldcs(p + tid + TPB * 2);
    float4 v3 = __ldcs(p + tid + TPB * 3);
    float4 v4 = __ldcs(p + tid + TPB * 4);
    float4 v5 = __ldcs(p + tid + TPB * 5);
    float4 v6 = __ldcs(p + tid + TPB * 6);
    float4 v7 = __ldcs(p + tid + TPB * 7);

    // Boundary rows (overlap with load latency)
    if (tid < 6 * D) {
        int m = tid / D, j = tid % D;
        int t = (m < 3) ? m : (L - 6 + m);  // 0,1,2,509,510,511
        xb[m * 32 + j] = se[(size_t)n * (L * D) + (size_t)t * D + j];
    }

    float4 acc;
    acc.x = ((v0.x + v1.x) + (v2.x + v3.x)) + ((v4.x + v5.x) + (v6.x + v7.x));
    acc.y = ((v0.y + v1.y) + (v2.y + v3.y)) + ((v4.y + v5.y) + (v6.y + v7.y));
    acc.z = ((v0.z + v1.z) + (v2.z + v3.z)) + ((v4.z + v5.z) + (v6.z + v7.z));
    acc.w = ((v0.w + v1.w) + (v2.w + v3.w)) + ((v4.w + v5.w) + (v6.w + v7.w));
    part4[tid] = acc;
    __syncthreads();

    // Deterministic channel reduce: slot k holds channel k % 30
    if (tid < 32) {
        const int o = tid;
        float s = 0.f;
        if (o < D) {
            const float* part = reinterpret_cast<const float*>(part4);
            #pragma unroll
            for (int k = 0; k < (TPB * 4) / D; k++)   // 64 partials, stride 30
                s += part[o + D * k];
        }
        S[o] = s;
        __syncwarp();

        const float inv515 = 1.f / (float)(L + 3);
        float s1 = 0.f, Tv = 0.f;
        if (o < D) {
            float ds = 0.f, bc = 0.f;
            #pragma unroll
            for (int j = 0; j < D; j++) ds += g_W1sum[o * D + j] * S[j];
            #pragma unroll
            for (int j = 0; j < D; j++) {
                const float* A = g_A1 + (o * D + j) * 6;
                #pragma unroll
                for (int m = 0; m < 6; m++) bc += A[m] * xb[m * 32 + j];
            }
            s1 = b1[o] + ds * inv515;
            Tv = (float)L * b1[o] + ds - 0.25f * bc;
        }
        T[o] = Tv;
        __syncwarp();

        float s2 = 0.f;
        if (o < D) {
            float d2 = 0.f;
            #pragma unroll
            for (int j = 0; j < D; j++) d2 += g_W2sum[o * D + j] * T[j];
            s2 = b2[o] + d2 * inv515;
        }

        float qr = 0.f, q1v = 0.f, q2v = 0.f;
        if (o < D) { qr = g_qraw[o]; q1v = g_q1g[o]; q2v = g_q2g[o]; }

        float p0 = s * qr, p1 = s * q2v, p2 = s * s;
        float p3 = s1 * q1v, p4 = s1 * s1, p5 = s2 * q2v, p6 = s2 * s2;
        #pragma unroll
        for (int off = 16; off; off >>= 1) {
            p0 += __shfl_down_sync(0xffffffffu, p0, off);
            p1 += __shfl_down_sync(0xffffffffu, p1, off);
            p2 += __shfl_down_sync(0xffffffffu, p2, off);
            p3 += __shfl_down_sync(0xffffffffu, p3, off);
            p4 += __shfl_down_sync(0xffffffffu, p4, off);
            p5 += __shfl_down_sync(0xffffffffu, p5, off);
            p6 += __shfl_down_sync(0xffffffffu, p6, off);
        }
        if (o == 0) {
            float inv_nS = rsqrtf(p2);
            float sim1 = (n == 0) ? (p0 * g_inv_nraw * inv_nS)
                                  : (p1 * g_inv_n2 * inv_nS);
            float sim2 = p3 * rsqrtf(p4) * g_inv_n1;
            float sim3 = p5 * rsqrtf(p6) * g_inv_n2;

            const float* g = gaf + (size_t)n * AF;
            float l0 = lb[0] + lw[0] * sim1 + lw[1] * sim2 + lw[2] * sim3;
            float l1 = lb[1] + lw[13] * sim1 + lw[14] * sim2 + lw[15] * sim3;
            #pragma unroll
            for (int f = 0; f < AF; f++) {
                float gv = g[f];
                l0 += lw[3 + f] * gv;
                l1 += lw[16 + f] * gv;
            }
            float mx = fmaxf(l0, l1);
            float lse = mx + logf(expf(l0 - mx) + expf(l1 - mx));
            float lp0 = l0 - lse, lp1 = l1 - lse;
            float e0 = expf(lp0), e1 = expf(lp1);
            out[1 + n] = e1 / (e0 + e1);
            int lab = labels[n];
            g_costs[n] = -(lab ? lp1 : lp0);
        }
    }

    // Last block: deterministic cost reduction
    __syncthreads();
    if (tid == 0) {
        __threadfence();
        int old = atomicAdd(&g_ctr, 1);
        last = (old == NSENT - 1) ? 1 : 0;
    }
    __syncthreads();
    if (last) {
        __threadfence();
        __shared__ float sm[256];
        if (tid < 256) {
            float s = 0.f;
            for (int i = tid; i < NSENT; i += 256) s += g_costs[i];
            sm[tid] = s;
        }
        __syncthreads();
        for (int w = 128; w; w >>= 1) {
            if (tid < w) sm[tid] += sm[tid + w];
            __syncthreads();
        }
        if (tid == 0) out[0] = sm[0] / (float)NSENT;
    }
}

// ---------------------------------------------------------------------------
extern "C" void kernel_launch(void* const* d_in, const int* in_sizes, int n_in,
                              void* d_out, int out_size)
{
    const float* se  = (const float*)d_in[0];
    const float* qe  = (const float*)d_in[1];
    const float* gaf = (const float*)d_in[2];
    const int*   lab = (const int*)d_in[3];
    const float* w1  = (const float*)d_in[4];
    const float* b1  = (const float*)d_in[5];
    const float* w2  = (const float*)d_in[6];
    const float* b2  = (const float*)d_in[7];
    const float* lw  = (const float*)d_in[8];
    const float* lb  = (const float*)d_in[9];
    float* out = (float*)d_out;

    prep_kernel<<<1, 960>>>(qe, w1, b1, w2, b2);
    fused_kernel<<<NSENT, TPB>>>(se, gaf, lab, b1, b2, lw, lb, out);
}

// round 12
// speedup vs baseline: 1.9274x; 1.9274x over previous
#include <cuda_runtime.h>
#include <cstdint>
#include <math.h>

// Shapes (fixed by the problem)
#define NSENT 4096
#define L     512
#define LQ    32
#define D     30
#define AF    10
#define KK    4

#define TPB_A 480   // 480*4 % 30 == 0 -> fixed channel phase per thread
#define TPB_B 256
#define NBLK_B (NSENT / 8)

__device__ float g_S[NSENT][D];
__device__ float g_costs[NSENT];
__device__ int   g_ctr;

// ---------------------------------------------------------------------------
// Kernel A: pure streaming column-sum. One block per sentence, nothing else.
// ---------------------------------------------------------------------------
__global__ __launch_bounds__(TPB_A, 4) void colsum_kernel(const float* __restrict__ se)
{
    __shared__ float4 part4[TPB_A];

    const int n = blockIdx.x;
    const int tid = threadIdx.x;

    if (n == 0 && tid == 0) g_ctr = 0;

    const float4* p = reinterpret_cast<const float4*>(se) + (size_t)n * (L * D / 4);

    // Batch 1: 4 loads in flight
    float4 v0 = __ldcs(p + tid + TPB_A * 0);
    float4 v1 = __ldcs(p + tid + TPB_A * 1);
    float4 v2 = __ldcs(p + tid + TPB_A * 2);
    float4 v3 = __ldcs(p + tid + TPB_A * 3);
    float ax = (v0.x + v1.x) + (v2.x + v3.x);
    float ay = (v0.y + v1.y) + (v2.y + v3.y);
    float az = (v0.z + v1.z) + (v2.z + v3.z);
    float aw = (v0.w + v1.w) + (v2.w + v3.w);

    // Batch 2
    float4 u0 = __ldcs(p + tid + TPB_A * 4);
    float4 u1 = __ldcs(p + tid + TPB_A * 5);
    float4 u2 = __ldcs(p + tid + TPB_A * 6);
    float4 u3 = __ldcs(p + tid + TPB_A * 7);
    ax += (u0.x + u1.x) + (u2.x + u3.x);
    ay += (u0.y + u1.y) + (u2.y + u3.y);
    az += (u0.z + u1.z) + (u2.z + u3.z);
    aw += (u0.w + u1.w) + (u2.w + u3.w);

    part4[tid] = make_float4(ax, ay, az, aw);
    __syncthreads();

    // Slot k holds channel k % 30; thread o sums its 64 partials.
    if (tid < D) {
        const float* part = reinterpret_cast<const float*>(part4);
        float s = 0.f;
        #pragma unroll
        for (int k = 0; k < (TPB_A * 4) / D; k++)
            s += part[tid + D * k];
        g_S[n][tid] = s;
    }
}

// ---------------------------------------------------------------------------
// Kernel B: tables + question side per block, 8 sentence tails per block,
// last-block deterministic cost reduction.
// ---------------------------------------------------------------------------
__global__ __launch_bounds__(TPB_B) void tail_kernel(
    const float* __restrict__ se, const float* __restrict__ qe,
    const float* __restrict__ gaf, const int* __restrict__ labels,
    const float* __restrict__ w1, const float* __restrict__ b1,
    const float* __restrict__ w2, const float* __restrict__ b2,
    const float* __restrict__ lw, const float* __restrict__ lb,
    float* __restrict__ out)
{
    __shared__ float sW1[D * D], sW2[D * D], sA[D * D * 6];
    __shared__ float q0[32], q1g[32], q2g[32];   // qraw(sum), conv1-gpool, conv2-gpool
    __shared__ float qn[3];                       // inverse norms
    __shared__ float sxq[6][32];                  // question boundary rows
    __shared__ float sS[8][32], sT[8][32], sxb[8][6][32];
    __shared__ int last;

    const int tid = threadIdx.x;
    const int w = tid / 32, o = tid % 32;

    // Stage coefficient tables (from raw weights, L2-hot across blocks)
    for (int i = tid; i < D * D; i += TPB_B) {
        const float* ww = w1 + i * KK;
        float a = ww[0], b = ww[1], c = ww[2], d = ww[3];
        sW1[i] = a + b + c + d;
        const float* vv = w2 + i * KK;
        sW2[i] = vv[0] + vv[1] + vv[2] + vv[3];
        float* A = sA + i * 6;
        A[0] = 3.f * d + 2.f * c + b;   // x[.,0]
        A[1] = 2.f * d + c;             // x[.,1]
        A[2] = d;                       // x[.,2]
        A[3] = a;                       // x[.,T-3]
        A[4] = 2.f * a + b;             // x[.,T-2]
        A[5] = 3.f * a + 2.f * b + c;   // x[.,T-1]
    }
    __syncthreads();

    // Warp 0: question side (redundant per block; ~1-2us, parallel over blocks)
    if (w == 0) {
        float Sq = 0.f;
        if (o < D) {
            #pragma unroll
            for (int t = 0; t < LQ; t++) Sq += qe[t * D + o];
            sxq[0][o] = qe[0 * D + o];
            sxq[1][o] = qe[1 * D + o];
            sxq[2][o] = qe[2 * D + o];
            sxq[3][o] = qe[(LQ - 3) * D + o];
            sxq[4][o] = qe[(LQ - 2) * D + o];
            sxq[5][o] = qe[(LQ - 1) * D + o];
        }
        q0[o] = (o < D) ? Sq : 0.f;
        __syncwarp();

        const float invLq3 = 1.f / (float)(LQ + 3);
        float q1 = 0.f, Tv = 0.f;
        if (o < D) {
            float ds = 0.f, bc = 0.f;
            #pragma unroll
            for (int j = 0; j < D; j++) ds += sW1[o * D + j] * q0[j];
            #pragma unroll
            for (int j = 0; j < D; j++) {
                const float* A = sA + (o * D + j) * 6;
                #pragma unroll
                for (int m = 0; m < 6; m++) bc += A[m] * sxq[m][j];
            }
            q1 = b1[o] + ds * invLq3;
            Tv = (float)LQ * b1[o] + ds - 0.25f * bc;
        }
        q1g[o] = q1;
        sT[0][o] = Tv;      // scratch before sentences use it? warp0 reuses below
        __syncwarp();

        float q2 = 0.f;
        if (o < D) {
            float d2 = 0.f;
            #pragma unroll
            for (int j = 0; j < D; j++) d2 += sW2[o * D + j] * sT[0][j];
            q2 = b2[o] + d2 * invLq3;
        }
        q2g[o] = q2;
        __syncwarp();

        float n0 = q0[o] * q0[o];
        float n1 = q1 * q1;
        float n2 = q2 * q2;
        #pragma unroll
        for (int off = 16; off; off >>= 1) {
            n0 += __shfl_down_sync(0xffffffffu, n0, off);
            n1 += __shfl_down_sync(0xffffffffu, n1, off);
            n2 += __shfl_down_sync(0xffffffffu, n2, off);
        }
        if (o == 0) {
            qn[0] = rsqrtf(n0);
            qn[1] = rsqrtf(n1);
            qn[2] = rsqrtf(n2);
        }
        __syncwarp();
    }

    // Every warp: one sentence tail (warp 0 after its question work; sT[0] reused)
    const int n = blockIdx.x * 8 + w;
    float Sv = 0.f;
    if (o < D) {
        Sv = g_S[n][o];
        const float* base = se + (size_t)n * (L * D);
        sxb[w][0][o] = base[0 * D + o];
        sxb[w][1][o] = base[1 * D + o];
        sxb[w][2][o] = base[2 * D + o];
        sxb[w][3][o] = base[(L - 3) * D + o];
        sxb[w][4][o] = base[(L - 2) * D + o];
        sxb[w][5][o] = base[(L - 1) * D + o];
    }
    sS[w][o] = Sv;
    __syncwarp();

    const float inv515 = 1.f / (float)(L + 3);
    float s1 = 0.f, Tv = 0.f;
    if (o < D) {
        float ds = 0.f, bc = 0.f;
        #pragma unroll
        for (int j = 0; j < D; j++) ds += sW1[o * D + j] * sS[w][j];
        #pragma unroll
        for (int j = 0; j < D; j++) {
            const float* A = sA + (o * D + j) * 6;
            #pragma unroll
            for (int m = 0; m < 6; m++) bc += A[m] * sxb[w][m][j];
        }
        s1 = b1[o] + ds * inv515;
        Tv = (float)L * b1[o] + ds - 0.25f * bc;
    }
    sT[w][o] = Tv;
    __syncwarp();

    float s2 = 0.f;
    if (o < D) {
        float d2 = 0.f;
        #pragma unroll
        for (int j = 0; j < D; j++) d2 += sW2[o * D + j] * sT[w][j];
        s2 = b2[o] + d2 * inv515;
    }

    __syncthreads();   // question-side results visible to all warps

    float qr = 0.f, q1v = 0.f, q2v = 0.f;
    if (o < D) { qr = q0[o]; q1v = q1g[o]; q2v = q2g[o]; }

    float p0 = Sv * qr, p1 = Sv * q2v, p2 = Sv * Sv;
    float p3 = s1 * q1v, p4 = s1 * s1, p5 = s2 * q2v, p6 = s2 * s2;
    #pragma unroll
    for (int off = 16; off; off >>= 1) {
        p0 += __shfl_down_sync(0xffffffffu, p0, off);
        p1 += __shfl_down_sync(0xffffffffu, p1, off);
        p2 += __shfl_down_sync(0xffffffffu, p2, off);
        p3 += __shfl_down_sync(0xffffffffu, p3, off);
        p4 += __shfl_down_sync(0xffffffffu, p4, off);
        p5 += __shfl_down_sync(0xffffffffu, p5, off);
        p6 += __shfl_down_sync(0xffffffffu, p6, off);
    }
    if (o == 0) {
        float inv_nS = rsqrtf(p2);
        float sim1 = (n == 0) ? (p0 * qn[0] * inv_nS)
                              : (p1 * qn[2] * inv_nS);
        float sim2 = p3 * rsqrtf(p4) * qn[1];
        float sim3 = p5 * rsqrtf(p6) * qn[2];

        const float* g = gaf + (size_t)n * AF;
        float l0 = lb[0] + lw[0] * sim1 + lw[1] * sim2 + lw[2] * sim3;
        float l1 = lb[1] + lw[13] * sim1 + lw[14] * sim2 + lw[15] * sim3;
        #pragma unroll
        for (int f = 0; f < AF; f++) {
            float gv = g[f];
            l0 += lw[3 + f] * gv;
            l1 += lw[16 + f] * gv;
        }
        float mx = fmaxf(l0, l1);
        float lse = mx + logf(expf(l0 - mx) + expf(l1 - mx));
        float lp0 = l0 - lse, lp1 = l1 - lse;
        float e0 = expf(lp0), e1 = expf(lp1);
        out[1 + n] = e1 / (e0 + e1);
        int lab = labels[n];
        g_costs[n] = -(lab ? lp1 : lp0);
    }

    // Last block: deterministic cost reduction
    __syncthreads();
    if (tid == 0) {
        __threadfence();
        int old = atomicAdd(&g_ctr, 1);
        last = (old == NBLK_B - 1) ? 1 : 0;
    }
    __syncthreads();
    if (last) {
        __threadfence();
        __shared__ float sm[TPB_B];
        float s = 0.f;
        for (int i = tid; i < NSENT; i += TPB_B) s += g_costs[i];
        sm[tid] = s;
        __syncthreads();
        for (int ww = TPB_B / 2; ww; ww >>= 1) {
            if (tid < ww) sm[tid] += sm[tid + ww];
            __syncthreads();
        }
        if (tid == 0) out[0] = sm[0] / (float)NSENT;
    }
}

// ---------------------------------------------------------------------------
extern "C" void kernel_launch(void* const* d_in, const int* in_sizes, int n_in,
                              void* d_out, int out_size)
{
    const float* se  = (const float*)d_in[0];
    const float* qe  = (const float*)d_in[1];
    const float* gaf = (const float*)d_in[2];
    const int*   lab = (const int*)d_in[3];
    const float* w1  = (const float*)d_in[4];
    const float* b1  = (const float*)d_in[5];
    const float* w2  = (const float*)d_in[6];
    const float* b2  = (const float*)d_in[7];
    const float* lw  = (const float*)d_in[8];
    const float* lb  = (const float*)d_in[9];
    float* out = (float*)d_out;

    colsum_kernel<<<NSENT, TPB_A>>>(se);
    tail_kernel<<<NBLK_B, TPB_B>>>(se, qe, gaf, lab, w1, b1, w2, b2, lw, lb, out);
}

// round 13
// speedup vs baseline: 2.1489x; 1.1149x over previous
#include <cuda_runtime.h>
#include <cstdint>
#include <math.h>

// Shapes (fixed by the problem)
#define NSENT 4096
#define L     512
#define LQ    32
#define D     30
#define AF    10
#define KK    4

#define TPB_A 480   // 480*4 % 30 == 0 -> fixed channel phase per thread
#define TPB_B 512
#define WARPS_B 16
#define NBLK_B (NSENT / WARPS_B)   // 256
#define PITCH 31                    // table row pitch (avoid bank conflicts)

__device__ float g_S[NSENT][D];
__device__ float g_costs[NSENT];
__device__ int   g_ctr;

// ---------------------------------------------------------------------------
// Kernel A: pure streaming column-sum. One block per sentence, nothing else.
// (measured at ~7.6 TB/s — do not touch)
// ---------------------------------------------------------------------------
__global__ __launch_bounds__(TPB_A, 4) void colsum_kernel(const float* __restrict__ se)
{
    __shared__ float4 part4[TPB_A];

    const int n = blockIdx.x;
    const int tid = threadIdx.x;

    if (n == 0 && tid == 0) g_ctr = 0;

    const float4* p = reinterpret_cast<const float4*>(se) + (size_t)n * (L * D / 4);

    float4 v0 = __ldcs(p + tid + TPB_A * 0);
    float4 v1 = __ldcs(p + tid + TPB_A * 1);
    float4 v2 = __ldcs(p + tid + TPB_A * 2);
    float4 v3 = __ldcs(p + tid + TPB_A * 3);
    float ax = (v0.x + v1.x) + (v2.x + v3.x);
    float ay = (v0.y + v1.y) + (v2.y + v3.y);
    float az = (v0.z + v1.z) + (v2.z + v3.z);
    float aw = (v0.w + v1.w) + (v2.w + v3.w);

    float4 u0 = __ldcs(p + tid + TPB_A * 4);
    float4 u1 = __ldcs(p + tid + TPB_A * 5);
    float4 u2 = __ldcs(p + tid + TPB_A * 6);
    float4 u3 = __ldcs(p + tid + TPB_A * 7);
    ax += (u0.x + u1.x) + (u2.x + u3.x);
    ay += (u0.y + u1.y) + (u2.y + u3.y);
    az += (u0.z + u1.z) + (u2.z + u3.z);
    aw += (u0.w + u1.w) + (u2.w + u3.w);

    part4[tid] = make_float4(ax, ay, az, aw);
    __syncthreads();

    if (tid < D) {
        const float* part = reinterpret_cast<const float*>(part4);
        float s = 0.f;
        #pragma unroll
        for (int k = 0; k < (TPB_A * 4) / D; k++)
            s += part[tid + D * k];
        g_S[n][tid] = s;
    }
}

// ---------------------------------------------------------------------------
// Boundary z-vector: bc[o] = sum_j dot(w1[o][j][0..3], z[j])
//   z = ( x3+2x4+3x5,  x0+x4+2x5,  2x0+x1+x5,  3x0+2x1+x2 )
// where x0..x2 = rows 0,1,2 and x3..x5 = rows T-3,T-2,T-1 of the input.
// ---------------------------------------------------------------------------
__device__ __forceinline__ float4 make_z(float x0, float x1, float x2,
                                         float x3, float x4, float x5)
{
    return make_float4(x3 + 2.f * x4 + 3.f * x5,
                       x0 + x4 + 2.f * x5,
                       2.f * x0 + x1 + x5,
                       3.f * x0 + 2.f * x1 + x2);
}

// ---------------------------------------------------------------------------
// Kernel B: 16 sentence tails per 512-thread block; raw-w float4 tables.
// ---------------------------------------------------------------------------
__global__ __launch_bounds__(TPB_B) void tail_kernel(
    const float* __restrict__ se, const float* __restrict__ qe,
    const float* __restrict__ gaf, const int* __restrict__ labels,
    const float* __restrict__ w1, const float* __restrict__ b1,
    const float* __restrict__ w2, const float* __restrict__ b2,
    const float* __restrict__ lw, const float* __restrict__ lb,
    float* __restrict__ out)
{
    __shared__ float4 sWv[D * PITCH];       // raw w1 taps (float4)
    __shared__ float  sW2s[D * PITCH];      // w2 tap-sums
    __shared__ float  q0[32], q1g[32], q2g[32], qT[32], qn[3];
    __shared__ float4 qzv[32];
    __shared__ float  sS[WARPS_B][32], sT[WARPS_B][32];
    __shared__ float4 zv4[WARPS_B][32];
    __shared__ int last;

    const int tid = threadIdx.x;
    const int w = tid / 32, o = tid % 32;

    // Stage tables from raw weights (L2-hot across blocks)
    for (int i = tid; i < D * D; i += TPB_B) {
        int oo = i / D, jj = i % D;
        const float4 wv = *reinterpret_cast<const float4*>(w1 + i * KK);
        sWv[oo * PITCH + jj] = wv;
        const float* vv = w2 + i * KK;
        sW2s[oo * PITCH + jj] = vv[0] + vv[1] + vv[2] + vv[3];
    }

    // Warp 0: question-side raw inputs (independent of tables)
    if (w == 0) {
        float Sq = 0.f;
        if (o < D) {
            #pragma unroll
            for (int t = 0; t < LQ; t++) Sq += qe[t * D + o];
            float x0 = qe[0 * D + o],        x1 = qe[1 * D + o],        x2 = qe[2 * D + o];
            float x3 = qe[(LQ - 3) * D + o], x4 = qe[(LQ - 2) * D + o], x5 = qe[(LQ - 1) * D + o];
            qzv[o] = make_z(x0, x1, x2, x3, x4, x5);
        }
        q0[o] = (o < D) ? Sq : 0.f;
    }

    // Every warp: load its sentence's column sums + boundary z (also table-free)
    const int n = blockIdx.x * WARPS_B + w;
    float Sv = 0.f;
    if (o < D) {
        Sv = g_S[n][o];
        const float* base = se + (size_t)n * (L * D);
        float x0 = base[0 * D + o],       x1 = base[1 * D + o],       x2 = base[2 * D + o];
        float x3 = base[(L - 3) * D + o], x4 = base[(L - 2) * D + o], x5 = base[(L - 1) * D + o];
        zv4[w][o] = make_z(x0, x1, x2, x3, x4, x5);
    }
    sS[w][o] = Sv;
    __syncthreads();   // tables + q inputs + per-warp S/z visible

    // Warp 0: question-side matvecs
    if (w == 0) {
        const float invLq3 = 1.f / (float)(LQ + 3);
        float q1 = 0.f, Tv = 0.f;
        if (o < D) {
            float ds = 0.f, bc = 0.f;
            #pragma unroll
            for (int j = 0; j < D; j++) {
                float4 wv = sWv[o * PITCH + j];
                float ws = (wv.x + wv.y) + (wv.z + wv.w);
                ds += ws * q0[j];
                float4 z = qzv[j];
                bc += wv.x * z.x + wv.y * z.y + wv.z * z.z + wv.w * z.w;
            }
            q1 = b1[o] + ds * invLq3;
            Tv = (float)LQ * b1[o] + ds - 0.25f * bc;
        }
        q1g[o] = q1;
        qT[o] = Tv;
        __syncwarp();

        float q2 = 0.f;
        if (o < D) {
            float d2 = 0.f;
            #pragma unroll
            for (int j = 0; j < D; j++) d2 += sW2s[o * PITCH + j] * qT[j];
            q2 = b2[o] + d2 * invLq3;
        }
        q2g[o] = q2;
        __syncwarp();

        float n0 = q0[o] * q0[o];
        float n1 = q1 * q1;
        float n2 = q2 * q2;
        #pragma unroll
        for (int off = 16; off; off >>= 1) {
            n0 += __shfl_down_sync(0xffffffffu, n0, off);
            n1 += __shfl_down_sync(0xffffffffu, n1, off);
            n2 += __shfl_down_sync(0xffffffffu, n2, off);
        }
        if (o == 0) {
            qn[0] = rsqrtf(n0);
            qn[1] = rsqrtf(n1);
            qn[2] = rsqrtf(n2);
        }
    }

    // Every warp: sentence-side matvecs
    const float inv515 = 1.f / (float)(L + 3);
    float s1 = 0.f, Tv = 0.f;
    if (o < D) {
        float ds = 0.f, bc = 0.f;
        #pragma unroll
        for (int j = 0; j < D; j++) {
            float4 wv = sWv[o * PITCH + j];
            float ws = (wv.x + wv.y) + (wv.z + wv.w);
            ds += ws * sS[w][j];
            float4 z = zv4[w][j];
            bc += wv.x * z.x + wv.y * z.y + wv.z * z.z + wv.w * z.w;
        }
        s1 = b1[o] + ds * inv515;
        Tv = (float)L * b1[o] + ds - 0.25f * bc;
    }
    sT[w][o] = Tv;
    __syncwarp();

    float s2 = 0.f;
    if (o < D) {
        float d2 = 0.f;
        #pragma unroll
        for (int j = 0; j < D; j++) d2 += sW2s[o * PITCH + j] * sT[w][j];
        s2 = b2[o] + d2 * inv515;
    }

    __syncthreads();   // question-side results (q0/q1g/q2g/qn) visible

    float qr = 0.f, q1v = 0.f, q2v = 0.f;
    if (o < D) { qr = q0[o]; q1v = q1g[o]; q2v = q2g[o]; }

    float p0 = Sv * qr, p1 = Sv * q2v, p2 = Sv * Sv;
    float p3 = s1 * q1v, p4 = s1 * s1, p5 = s2 * q2v, p6 = s2 * s2;
    #pragma unroll
    for (int off = 16; off; off >>= 1) {
        p0 += __shfl_down_sync(0xffffffffu, p0, off);
        p1 += __shfl_down_sync(0xffffffffu, p1, off);
        p2 += __shfl_down_sync(0xffffffffu, p2, off);
        p3 += __shfl_down_sync(0xffffffffu, p3, off);
        p4 += __shfl_down_sync(0xffffffffu, p4, off);
        p5 += __shfl_down_sync(0xffffffffu, p5, off);
        p6 += __shfl_down_sync(0xffffffffu, p6, off);
    }
    if (o == 0) {
        float inv_nS = rsqrtf(p2);
        float sim1 = (n == 0) ? (p0 * qn[0] * inv_nS)
                              : (p1 * qn[2] * inv_nS);
        float sim2 = p3 * rsqrtf(p4) * qn[1];
        float sim3 = p5 * rsqrtf(p6) * qn[2];

        const float* g = gaf + (size_t)n * AF;
        float l0 = lb[0] + lw[0] * sim1 + lw[1] * sim2 + lw[2] * sim3;
        float l1 = lb[1] + lw[13] * sim1 + lw[14] * sim2 + lw[15] * sim3;
        #pragma unroll
        for (int f = 0; f < AF; f++) {
            float gv = g[f];
            l0 += lw[3 + f] * gv;
            l1 += lw[16 + f] * gv;
        }
        float mx = fmaxf(l0, l1);
        float lse = mx + logf(expf(l0 - mx) + expf(l1 - mx));
        float lp0 = l0 - lse, lp1 = l1 - lse;
        float e0 = expf(lp0), e1 = expf(lp1);
        out[1 + n] = e1 / (e0 + e1);
        int lab = labels[n];
        g_costs[n] = -(lab ? lp1 : lp0);
    }

    // Last block: deterministic cost reduction
    __syncthreads();
    if (tid == 0) {
        __threadfence();
        int old = atomicAdd(&g_ctr, 1);
        last = (old == NBLK_B - 1) ? 1 : 0;
    }
    __syncthreads();
    if (last) {
        __threadfence();
        __shared__ float sm[TPB_B];
        float s = 0.f;
        for (int i = tid; i < NSENT; i += TPB_B) s += g_costs[i];
        sm[tid] = s;
        __syncthreads();
        for (int ww = TPB_B / 2; ww; ww >>= 1) {
            if (tid < ww) sm[tid] += sm[tid + ww];
            __syncthreads();
        }
        if (tid == 0) out[0] = sm[0] / (float)NSENT;
    }
}

// ---------------------------------------------------------------------------
extern "C" void kernel_launch(void* const* d_in, const int* in_sizes, int n_in,
                              void* d_out, int out_size)
{
    const float* se  = (const float*)d_in[0];
    const float* qe  = (const float*)d_in[1];
    const float* gaf = (const float*)d_in[2];
    const int*   lab = (const int*)d_in[3];
    const float* w1  = (const float*)d_in[4];
    const float* b1  = (const float*)d_in[5];
    const float* w2  = (const float*)d_in[6];
    const float* b2  = (const float*)d_in[7];
    const float* lw  = (const float*)d_in[8];
    const float* lb  = (const float*)d_in[9];
    float* out = (float*)d_out;

    colsum_kernel<<<NSENT, TPB_A>>>(se);
    tail_kernel<<<NBLK_B, TPB_B>>>(se, qe, gaf, lab, w1, b1, w2, b2, lw, lb, out);
}